// round 2
// baseline (speedup 1.0000x reference)
#include <cuda_runtime.h>
#include <math.h>

// Problem dims
#define BB 2
#define SS 2048
#define DM 1024
#define HH 16
#define DK 64
#define MTOT (BB*SS)   // 4096

// fp32 scratch: Q,K,V,ctx each [B,H,S,64] = 4M floats = 16MB
__device__ float g_Q[(size_t)BB*HH*SS*DK];
__device__ float g_K[(size_t)BB*HH*SS*DK];
__device__ float g_V[(size_t)BB*HH*SS*DK];
__device__ float g_C[(size_t)BB*HH*SS*DK];

// ---------------------------------------------------------------------------
// Kernel 1: fused QKV projection.
// grid = (MTOT/128, 48). z = blockIdx.y: [0,16)=Q, [16,32)=K, [32,48)=V, head = z&15.
// GEMM tile: BM=128, BN=64 (full head), BK=16; 256 threads, 8x4 microtile.
// ---------------------------------------------------------------------------
__global__ __launch_bounds__(256) void qkv_kernel(const float* __restrict__ x,
                                                  const float* __restrict__ Wq,
                                                  const float* __restrict__ Wk,
                                                  const float* __restrict__ Wv) {
    __shared__ float As[16][132];   // k-major, padded (132*4B rows stay 16B aligned)
    __shared__ float Bs[16][64];

    const int z   = blockIdx.y;
    const int mat = z >> 4;
    const int h   = z & 15;
    const int m0  = blockIdx.x * 128;

    const float* W   = (mat == 0 ? Wq : (mat == 1 ? Wk : Wv)) + (size_t)h * DM * DK;
    float*       Out = (mat == 0 ? g_Q : (mat == 1 ? g_K : g_V));

    const int t  = threadIdx.x;
    const int tx = t & 15;     // 4 cols each  -> 64
    const int ty = t >> 4;     // 8 rows each  -> 128

    float acc[8][4];
#pragma unroll
    for (int i = 0; i < 8; i++)
#pragma unroll
        for (int j = 0; j < 4; j++) acc[i][j] = 0.f;

    for (int k0 = 0; k0 < DM; k0 += 16) {
        // A tile: 128x16, transpose into As[k][m]
#pragma unroll
        for (int i = 0; i < 2; i++) {
            int j   = t + i * 256;          // float4 index, 512 total
            int row = j >> 2;
            int c4  = (j & 3) * 4;
            float4 v = *(const float4*)&x[(size_t)(m0 + row) * DM + k0 + c4];
            As[c4 + 0][row] = v.x;
            As[c4 + 1][row] = v.y;
            As[c4 + 2][row] = v.z;
            As[c4 + 3][row] = v.w;
        }
        // B tile: 16x64 direct
        {
            int kr = t >> 4;
            int c4 = (t & 15) * 4;
            *(float4*)&Bs[kr][c4] = *(const float4*)&W[(size_t)(k0 + kr) * DK + c4];
        }
        __syncthreads();

#pragma unroll
        for (int k = 0; k < 16; k++) {
            float a[8], b[4];
            *(float4*)&a[0] = *(const float4*)&As[k][ty * 8];
            *(float4*)&a[4] = *(const float4*)&As[k][ty * 8 + 4];
            *(float4*)&b[0] = *(const float4*)&Bs[k][tx * 4];
#pragma unroll
            for (int i = 0; i < 8; i++)
#pragma unroll
                for (int j = 0; j < 4; j++) acc[i][j] += a[i] * b[j];
        }
        __syncthreads();
    }

    // store: [B,H,S,64] layout
#pragma unroll
    for (int i = 0; i < 8; i++) {
        int m = m0 + ty * 8 + i;
        int b = m >> 11;
        int s = m & 2047;
        float* o = &Out[(((size_t)(b * HH + h)) * SS + s) * DK + tx * 4];
        float4 v;
        v.x = acc[i][0]; v.y = acc[i][1]; v.z = acc[i][2]; v.w = acc[i][3];
        *(float4*)o = v;
    }
}

// ---------------------------------------------------------------------------
// Kernel 2: flash attention, fp32, online softmax.
// grid = (S/64, B*H). 256 threads. BR=BC=64.
// thread t: row r = t>>2, sub = t&3. Score cols owned: c = sub + 4*i (i<16).
// Output dims owned: d = sub*16 .. +16.
// Dynamic smem: Qs,Ks,Vs,Ps each [64][68] floats = 69,632 B.
// ---------------------------------------------------------------------------
__global__ __launch_bounds__(256) void attn_kernel() {
    extern __shared__ float smem[];
    float (*Qs)[68] = (float(*)[68])(smem);
    float (*Ks)[68] = (float(*)[68])(smem + 64 * 68);
    float (*Vs)[68] = (float(*)[68])(smem + 2 * 64 * 68);
    float (*Ps)[68] = (float(*)[68])(smem + 3 * 64 * 68);

    const int bh = blockIdx.y;
    const int q0 = blockIdx.x * 64;
    const int t  = threadIdx.x;
    const int r   = t >> 2;
    const int sub = t & 3;

    const float* Qg = g_Q + (size_t)bh * SS * DK;
    const float* Kg = g_K + (size_t)bh * SS * DK;
    const float* Vg = g_V + (size_t)bh * SS * DK;

    // load Q tile, pre-scaled by 1/sqrt(64)
#pragma unroll
    for (int i = 0; i < 4; i++) {
        int j   = t + i * 256;          // 1024 float4s total
        int row = j >> 4;
        int c4  = (j & 15) * 4;
        float4 v = *(const float4*)&Qg[(size_t)(q0 + row) * DK + c4];
        v.x *= 0.125f; v.y *= 0.125f; v.z *= 0.125f; v.w *= 0.125f;
        *(float4*)&Qs[row][c4] = v;
    }

    float m_run = -3.0e38f;
    float l_run = 0.f;
    float acc[16];
#pragma unroll
    for (int i = 0; i < 16; i++) acc[i] = 0.f;

    for (int t0 = 0; t0 < SS; t0 += 64) {
        __syncthreads();   // prev PV done with Ks/Vs/Ps (also covers Q load, iter 0)
#pragma unroll
        for (int i = 0; i < 4; i++) {
            int j   = t + i * 256;
            int row = j >> 4;
            int c4  = (j & 15) * 4;
            *(float4*)&Ks[row][c4] = *(const float4*)&Kg[(size_t)(t0 + row) * DK + c4];
            *(float4*)&Vs[row][c4] = *(const float4*)&Vg[(size_t)(t0 + row) * DK + c4];
        }
        __syncthreads();

        // scores for cols c = sub + 4*i
        float s[16];
#pragma unroll
        for (int i = 0; i < 16; i++) s[i] = 0.f;
#pragma unroll
        for (int kg = 0; kg < 16; kg++) {
            float4 q = *(const float4*)&Qs[r][kg * 4];
#pragma unroll
            for (int i = 0; i < 16; i++) {
                float4 kk = *(const float4*)&Ks[sub + 4 * i][kg * 4];
                s[i] += q.x * kk.x;
                s[i] += q.y * kk.y;
                s[i] += q.z * kk.z;
                s[i] += q.w * kk.w;
            }
        }

        // online softmax update
        float mloc = s[0];
#pragma unroll
        for (int i = 1; i < 16; i++) mloc = fmaxf(mloc, s[i]);
        mloc = fmaxf(mloc, __shfl_xor_sync(0xffffffffu, mloc, 1));
        mloc = fmaxf(mloc, __shfl_xor_sync(0xffffffffu, mloc, 2));
        float mnew = fmaxf(m_run, mloc);
        float corr = __expf(m_run - mnew);
        float lloc = 0.f;
#pragma unroll
        for (int i = 0; i < 16; i++) {
            s[i] = __expf(s[i] - mnew);
            lloc += s[i];
        }
        lloc += __shfl_xor_sync(0xffffffffu, lloc, 1);
        lloc += __shfl_xor_sync(0xffffffffu, lloc, 2);
        l_run = l_run * corr + lloc;
        m_run = mnew;
#pragma unroll
        for (int i = 0; i < 16; i++) acc[i] *= corr;

        // publish probabilities (conflict-free: bank = (4r+sub+4i)%32 distinct)
#pragma unroll
        for (int i = 0; i < 16; i++) Ps[r][sub + 4 * i] = s[i];
        __syncthreads();

        // PV: acc[d] += sum_c P[r][c] * V[c][d], d = sub*16..+16
#pragma unroll 8
        for (int c = 0; c < 64; c++) {
            float p = Ps[r][c];
            const float* vrow = &Vs[c][sub * 16];
            float4 v0 = *(const float4*)&vrow[0];
            float4 v1 = *(const float4*)&vrow[4];
            float4 v2 = *(const float4*)&vrow[8];
            float4 v3 = *(const float4*)&vrow[12];
            acc[0]  += p * v0.x; acc[1]  += p * v0.y; acc[2]  += p * v0.z; acc[3]  += p * v0.w;
            acc[4]  += p * v1.x; acc[5]  += p * v1.y; acc[6]  += p * v1.z; acc[7]  += p * v1.w;
            acc[8]  += p * v2.x; acc[9]  += p * v2.y; acc[10] += p * v2.z; acc[11] += p * v2.w;
            acc[12] += p * v3.x; acc[13] += p * v3.y; acc[14] += p * v3.z; acc[15] += p * v3.w;
        }
    }

    float inv = 1.f / l_run;
    float* o = g_C + ((size_t)bh * SS + q0 + r) * DK + sub * 16;
#pragma unroll
    for (int u = 0; u < 4; u++) {
        float4 v;
        v.x = acc[u * 4 + 0] * inv;
        v.y = acc[u * 4 + 1] * inv;
        v.z = acc[u * 4 + 2] * inv;
        v.w = acc[u * 4 + 3] * inv;
        *(float4*)&o[u * 4] = v;
    }
}

// ---------------------------------------------------------------------------
// Kernel 3: output projection. out[m,n] = sum_c ctx[m,c] * Wo[c,n]
// ctx gathered from g_C's [B,H,S,64] layout. Tile 128x128x16, 8x8 microtile.
// grid = (MTOT/128, DM/128).
// ---------------------------------------------------------------------------
__global__ __launch_bounds__(256) void outproj_kernel(const float* __restrict__ Wo,
                                                      float* __restrict__ out) {
    __shared__ float As[16][132];
    __shared__ float Bs[16][128];

    const int m0 = blockIdx.x * 128;
    const int n0 = blockIdx.y * 128;
    const int t  = threadIdx.x;
    const int tx = t & 15;
    const int ty = t >> 4;

    float acc[8][8];
#pragma unroll
    for (int i = 0; i < 8; i++)
#pragma unroll
        for (int j = 0; j < 8; j++) acc[i][j] = 0.f;

    for (int k0 = 0; k0 < DM; k0 += 16) {
        // A gather (transpose into As[k][m])
#pragma unroll
        for (int i = 0; i < 2; i++) {
            int j   = t + i * 256;
            int row = j >> 2;
            int c4  = (j & 3) * 4;
            int m = m0 + row;
            int c = k0 + c4;
            int b = m >> 11, s = m & 2047, h = c >> 6, cv = c & 63;
            float4 v = *(const float4*)&g_C[(((size_t)(b * HH + h)) * SS + s) * DK + cv];
            As[c4 + 0][row] = v.x;
            As[c4 + 1][row] = v.y;
            As[c4 + 2][row] = v.z;
            As[c4 + 3][row] = v.w;
        }
        // B tile direct
#pragma unroll
        for (int i = 0; i < 2; i++) {
            int j  = t + i * 256;
            int kr = j >> 5;
            int c4 = (j & 31) * 4;
            *(float4*)&Bs[kr][c4] = *(const float4*)&Wo[(size_t)(k0 + kr) * DM + n0 + c4];
        }
        __syncthreads();

#pragma unroll
        for (int k = 0; k < 16; k++) {
            float a[8], b[8];
            *(float4*)&a[0] = *(const float4*)&As[k][ty * 8];
            *(float4*)&a[4] = *(const float4*)&As[k][ty * 8 + 4];
            *(float4*)&b[0] = *(const float4*)&Bs[k][tx * 8];
            *(float4*)&b[4] = *(const float4*)&Bs[k][tx * 8 + 4];
#pragma unroll
            for (int i = 0; i < 8; i++)
#pragma unroll
                for (int j = 0; j < 8; j++) acc[i][j] += a[i] * b[j];
        }
        __syncthreads();
    }

#pragma unroll
    for (int i = 0; i < 8; i++) {
        float* o = &out[(size_t)(m0 + ty * 8 + i) * DM + n0 + tx * 8];
        float4 v0, v1;
        v0.x = acc[i][0]; v0.y = acc[i][1]; v0.z = acc[i][2]; v0.w = acc[i][3];
        v1.x = acc[i][4]; v1.y = acc[i][5]; v1.z = acc[i][6]; v1.w = acc[i][7];
        *(float4*)&o[0] = v0;
        *(float4*)&o[4] = v1;
    }
}

// ---------------------------------------------------------------------------
// launch
// ---------------------------------------------------------------------------
extern "C" void kernel_launch(void* const* d_in, const int* in_sizes, int n_in,
                              void* d_out, int out_size) {
    // metadata order (setup_inputs dict): x, Wk, Wq, Wv, Wo
    const float* x  = (const float*)d_in[0];
    const float* Wk = (const float*)d_in[1];
    const float* Wq = (const float*)d_in[2];
    const float* Wv = (const float*)d_in[3];
    const float* Wo = (const float*)d_in[4];
    float* out = (float*)d_out;

    static int attn_smem_set = 0;
    const size_t attn_smem = 4 * 64 * 68 * sizeof(float);   // 69,632 B
    if (!attn_smem_set) {
        cudaFuncSetAttribute(attn_kernel, cudaFuncAttributeMaxDynamicSharedMemorySize,
                             (int)attn_smem);
        attn_smem_set = 1;
    }

    qkv_kernel<<<dim3(MTOT / 128, 48), 256>>>(x, Wq, Wk, Wv);
    attn_kernel<<<dim3(SS / 64, BB * HH), 256, attn_smem>>>();
    outproj_kernel<<<dim3(MTOT / 128, DM / 128), 256>>>(Wo, out);
}

// round 5
// speedup vs baseline: 1.0131x; 1.0131x over previous
#include <cuda_runtime.h>
#include <math.h>

typedef unsigned long long ull;

// Problem dims
#define BB 2
#define SS 2048
#define DM 1024
#define HH 16
#define DK 64
#define MTOT (BB*SS)   // 4096

// fp32 scratch: Q,K,V,ctx each [B,H,S,64] = 4M floats = 16MB
__device__ float g_Q[(size_t)BB*HH*SS*DK];
__device__ float g_K[(size_t)BB*HH*SS*DK];
__device__ float g_V[(size_t)BB*HH*SS*DK];
__device__ float g_C[(size_t)BB*HH*SS*DK];

// ---------------- f32x2 helpers (FFMA2 path, full fp32 precision) ----------
__device__ __forceinline__ ull pack2(float lo, float hi) {
    ull r; asm("mov.b64 %0, {%1, %2};" : "=l"(r) : "f"(lo), "f"(hi)); return r;
}
__device__ __forceinline__ float2 unpack2(ull v) {
    float2 r; asm("mov.b64 {%0, %1}, %2;" : "=f"(r.x), "=f"(r.y) : "l"(v)); return r;
}
__device__ __forceinline__ void fma2(ull& d, ull a, ull b) {
    asm("fma.rn.f32x2 %0, %1, %2, %0;" : "+l"(d) : "l"(a), "l"(b));
}
__device__ __forceinline__ ull mul2(ull a, ull b) {
    ull d; asm("mul.rn.f32x2 %0, %1, %2;" : "=l"(d) : "l"(a), "l"(b)); return d;
}

// ---------------------------------------------------------------------------
// Kernel 1: fused QKV projection.
// grid = (MTOT/128, 48). z: [0,16)=Q, [16,32)=K, [32,48)=V, head = z&15.
// Tile BM=128, BN=64, BK=32; 256 threads; microtile 8x4 held as 4x4 f32x2
// pairs (paired over M).
// ---------------------------------------------------------------------------
__global__ __launch_bounds__(256) void qkv_kernel(const float* __restrict__ x,
                                                  const float* __restrict__ Wq,
                                                  const float* __restrict__ Wk,
                                                  const float* __restrict__ Wv) {
    __shared__ float As[32][132];   // k-major, padded; row stride 528B (8B-aligned)
    __shared__ float Bs[32][64];

    const int z   = blockIdx.y;
    const int mat = z >> 4;
    const int h   = z & 15;
    const int m0  = blockIdx.x * 128;

    const float* W   = (mat == 0 ? Wq : (mat == 1 ? Wk : Wv)) + (size_t)h * DM * DK;
    float*       Out = (mat == 0 ? g_Q : (mat == 1 ? g_K : g_V));

    const int t  = threadIdx.x;
    const int tx = t & 15;     // 4 cols each  -> 64
    const int ty = t >> 4;     // 8 rows each  -> 128

    ull acc2[4][4];            // [mpair][j]: (row 2p, row 2p+1) x col j
#pragma unroll
    for (int p = 0; p < 4; p++)
#pragma unroll
        for (int j = 0; j < 4; j++) acc2[p][j] = 0ull;

    for (int k0 = 0; k0 < DM; k0 += 32) {
        // A tile: 128x32, transpose into As[k][m]. 1024 float4s, 4 per thread.
#pragma unroll
        for (int i = 0; i < 4; i++) {
            int j   = t + i * 256;
            int row = j >> 3;
            int c4  = (j & 7) * 4;
            float4 v = *(const float4*)&x[(size_t)(m0 + row) * DM + k0 + c4];
            As[c4 + 0][row] = v.x;
            As[c4 + 1][row] = v.y;
            As[c4 + 2][row] = v.z;
            As[c4 + 3][row] = v.w;
        }
        // B tile: 32x64, 512 float4s, 2 per thread.
#pragma unroll
        for (int i = 0; i < 2; i++) {
            int j  = t + i * 256;
            int kr = j >> 4;
            int c4 = (j & 15) * 4;
            *(float4*)&Bs[kr][c4] = *(const float4*)&W[(size_t)(k0 + kr) * DK + c4];
        }
        __syncthreads();

#pragma unroll
        for (int k = 0; k < 32; k++) {
            const ull* ap = (const ull*)&As[k][ty * 8];
            ull a0 = ap[0], a1 = ap[1], a2 = ap[2], a3 = ap[3];
            float4 bf = *(const float4*)&Bs[k][tx * 4];
            ull b0 = pack2(bf.x, bf.x);
            ull b1 = pack2(bf.y, bf.y);
            ull b2 = pack2(bf.z, bf.z);
            ull b3 = pack2(bf.w, bf.w);
            fma2(acc2[0][0], a0, b0); fma2(acc2[0][1], a0, b1);
            fma2(acc2[0][2], a0, b2); fma2(acc2[0][3], a0, b3);
            fma2(acc2[1][0], a1, b0); fma2(acc2[1][1], a1, b1);
            fma2(acc2[1][2], a1, b2); fma2(acc2[1][3], a1, b3);
            fma2(acc2[2][0], a2, b0); fma2(acc2[2][1], a2, b1);
            fma2(acc2[2][2], a2, b2); fma2(acc2[2][3], a2, b3);
            fma2(acc2[3][0], a3, b0); fma2(acc2[3][1], a3, b1);
            fma2(acc2[3][2], a3, b2); fma2(acc2[3][3], a3, b3);
        }
        __syncthreads();
    }

    // store: [B,H,S,64] layout
#pragma unroll
    for (int p = 0; p < 4; p++) {
        float2 c0 = unpack2(acc2[p][0]);
        float2 c1 = unpack2(acc2[p][1]);
        float2 c2 = unpack2(acc2[p][2]);
        float2 c3 = unpack2(acc2[p][3]);
        int m = m0 + ty * 8 + 2 * p;
        int b = m >> 11;
        int s = m & 2047;
        float* o = &Out[(((size_t)(b * HH + h)) * SS + s) * DK + tx * 4];
        float4 v;
        v.x = c0.x; v.y = c1.x; v.z = c2.x; v.w = c3.x;
        *(float4*)o = v;
        v.x = c0.y; v.y = c1.y; v.z = c2.y; v.w = c3.y;
        *(float4*)(o + DK) = v;   // row m+1, same b (m even, rows pair within batch)
    }
}

// ---------------------------------------------------------------------------
// Kernel 2: flash attention, fp32, online softmax, f32x2 math.
// grid = (S/64, B*H). 256 threads. BR=BC=64.
// thread t: row r = t>>2, sub = t&3. Score cols: c = sub + 4*i (i<16).
// Output dims owned: d = sub*16 .. +16.
// Dynamic smem: Qs,Ks,Vs,Ps each [64][68] floats = 69,632 B.
// ---------------------------------------------------------------------------
__global__ __launch_bounds__(256) void attn_kernel() {
    extern __shared__ float smem[];
    float (*Qs)[68] = (float(*)[68])(smem);
    float (*Ks)[68] = (float(*)[68])(smem + 64 * 68);
    float (*Vs)[68] = (float(*)[68])(smem + 2 * 64 * 68);
    float (*Ps)[68] = (float(*)[68])(smem + 3 * 64 * 68);

    const int bh = blockIdx.y;
    const int q0 = blockIdx.x * 64;
    const int t  = threadIdx.x;
    const int r   = t >> 2;
    const int sub = t & 3;

    const float* Qg = g_Q + (size_t)bh * SS * DK;
    const float* Kg = g_K + (size_t)bh * SS * DK;
    const float* Vg = g_V + (size_t)bh * SS * DK;

    // load Q tile, pre-scaled by 1/sqrt(64)
#pragma unroll
    for (int i = 0; i < 4; i++) {
        int j   = t + i * 256;
        int row = j >> 4;
        int c4  = (j & 15) * 4;
        float4 v = *(const float4*)&Qg[(size_t)(q0 + row) * DK + c4];
        v.x *= 0.125f; v.y *= 0.125f; v.z *= 0.125f; v.w *= 0.125f;
        *(float4*)&Qs[row][c4] = v;
    }

    float m_run = -3.0e38f;
    float l_run = 0.f;
    ull acc2[8];               // pairs over d: acc2[u] = (d=sub*16+2u, +1)
#pragma unroll
    for (int u = 0; u < 8; u++) acc2[u] = 0ull;

    for (int t0 = 0; t0 < SS; t0 += 64) {
        __syncthreads();   // prev PV done with Ks/Vs/Ps (also covers Q load, iter 0)
#pragma unroll
        for (int i = 0; i < 4; i++) {
            int j   = t + i * 256;
            int row = j >> 4;
            int c4  = (j & 15) * 4;
            *(float4*)&Ks[row][c4] = *(const float4*)&Kg[(size_t)(t0 + row) * DK + c4];
            *(float4*)&Vs[row][c4] = *(const float4*)&Vg[(size_t)(t0 + row) * DK + c4];
        }
        __syncthreads();

        // scores for cols c = sub + 4*i, paired over k-dim
        ull s2[16];
#pragma unroll
        for (int i = 0; i < 16; i++) s2[i] = 0ull;
#pragma unroll
        for (int kg = 0; kg < 16; kg++) {
            const ull* qp = (const ull*)&Qs[r][kg * 4];
            ull qa = qp[0], qb = qp[1];
#pragma unroll
            for (int i = 0; i < 16; i++) {
                const ull* kp = (const ull*)&Ks[sub + 4 * i][kg * 4];
                fma2(s2[i], qa, kp[0]);
                fma2(s2[i], qb, kp[1]);
            }
        }
        float s[16];
#pragma unroll
        for (int i = 0; i < 16; i++) {
            float2 u = unpack2(s2[i]);
            s[i] = u.x + u.y;
        }

        // online softmax update
        float mloc = s[0];
#pragma unroll
        for (int i = 1; i < 16; i++) mloc = fmaxf(mloc, s[i]);
        mloc = fmaxf(mloc, __shfl_xor_sync(0xffffffffu, mloc, 1));
        mloc = fmaxf(mloc, __shfl_xor_sync(0xffffffffu, mloc, 2));
        float mnew = fmaxf(m_run, mloc);
        float corr = __expf(m_run - mnew);
        float lloc = 0.f;
#pragma unroll
        for (int i = 0; i < 16; i++) {
            s[i] = __expf(s[i] - mnew);
            lloc += s[i];
        }
        lloc += __shfl_xor_sync(0xffffffffu, lloc, 1);
        lloc += __shfl_xor_sync(0xffffffffu, lloc, 2);
        l_run = l_run * corr + lloc;
        m_run = mnew;
        {
            ull cc = pack2(corr, corr);
#pragma unroll
            for (int u = 0; u < 8; u++) acc2[u] = mul2(acc2[u], cc);
        }

        // publish probabilities (conflict-free: bank = (4r+sub+4i)%32 distinct)
#pragma unroll
        for (int i = 0; i < 16; i++) Ps[r][sub + 4 * i] = s[i];
        __syncthreads();

        // PV: acc[d] += sum_c P[r][c] * V[c][d], d paired
#pragma unroll 8
        for (int c = 0; c < 64; c++) {
            float p = Ps[r][c];
            ull pp = pack2(p, p);
            const ull* vp = (const ull*)&Vs[c][sub * 16];
            fma2(acc2[0], pp, vp[0]);
            fma2(acc2[1], pp, vp[1]);
            fma2(acc2[2], pp, vp[2]);
            fma2(acc2[3], pp, vp[3]);
            fma2(acc2[4], pp, vp[4]);
            fma2(acc2[5], pp, vp[5]);
            fma2(acc2[6], pp, vp[6]);
            fma2(acc2[7], pp, vp[7]);
        }
    }

    float inv = 1.f / l_run;
    ull iv = pack2(inv, inv);
    float* o = g_C + ((size_t)bh * SS + q0 + r) * DK + sub * 16;
#pragma unroll
    for (int u = 0; u < 4; u++) {
        float2 e0 = unpack2(mul2(acc2[2 * u], iv));
        float2 e1 = unpack2(mul2(acc2[2 * u + 1], iv));
        float4 v;
        v.x = e0.x; v.y = e0.y; v.z = e1.x; v.w = e1.y;
        *(float4*)&o[u * 4] = v;
    }
}

// ---------------------------------------------------------------------------
// Kernel 3: output projection. out[m,n] = sum_c ctx[m,c] * Wo[c,n]
// Tile 128x128x32; microtile 8x8 held as 4x8 f32x2 pairs (paired over M).
// grid = (MTOT/128, DM/128).
// ---------------------------------------------------------------------------
__global__ __launch_bounds__(256) void outproj_kernel(const float* __restrict__ Wo,
                                                      float* __restrict__ out) {
    __shared__ float As[32][132];
    __shared__ float Bs[32][128];

    const int m0 = blockIdx.x * 128;
    const int n0 = blockIdx.y * 128;
    const int t  = threadIdx.x;
    const int tx = t & 15;
    const int ty = t >> 4;

    ull acc2[4][8];
#pragma unroll
    for (int p = 0; p < 4; p++)
#pragma unroll
        for (int j = 0; j < 8; j++) acc2[p][j] = 0ull;

    for (int k0 = 0; k0 < DM; k0 += 32) {
        // A gather (transpose into As[k][m]) from g_C's [B,H,S,64] layout
#pragma unroll
        for (int i = 0; i < 4; i++) {
            int j   = t + i * 256;
            int row = j >> 3;
            int c4  = (j & 7) * 4;
            int m = m0 + row;
            int c = k0 + c4;
            int b = m >> 11, s = m & 2047, h = c >> 6, cv = c & 63;
            float4 v = *(const float4*)&g_C[(((size_t)(b * HH + h)) * SS + s) * DK + cv];
            As[c4 + 0][row] = v.x;
            As[c4 + 1][row] = v.y;
            As[c4 + 2][row] = v.z;
            As[c4 + 3][row] = v.w;
        }
        // B tile 32x128 direct
#pragma unroll
        for (int i = 0; i < 4; i++) {
            int j  = t + i * 256;
            int kr = j >> 5;
            int c4 = (j & 31) * 4;
            *(float4*)&Bs[kr][c4] = *(const float4*)&Wo[(size_t)(k0 + kr) * DM + n0 + c4];
        }
        __syncthreads();

#pragma unroll
        for (int k = 0; k < 32; k++) {
            const ull* ap = (const ull*)&As[k][ty * 8];
            ull a0 = ap[0], a1 = ap[1], a2 = ap[2], a3 = ap[3];
            float4 bf0 = *(const float4*)&Bs[k][tx * 8];
            float4 bf1 = *(const float4*)&Bs[k][tx * 8 + 4];
            ull b0 = pack2(bf0.x, bf0.x);
            ull b1 = pack2(bf0.y, bf0.y);
            ull b2 = pack2(bf0.z, bf0.z);
            ull b3 = pack2(bf0.w, bf0.w);
            ull b4 = pack2(bf1.x, bf1.x);
            ull b5 = pack2(bf1.y, bf1.y);
            ull b6 = pack2(bf1.z, bf1.z);
            ull b7 = pack2(bf1.w, bf1.w);
#pragma unroll
            for (int p = 0; p < 4; p++) {
                ull a = (p == 0 ? a0 : p == 1 ? a1 : p == 2 ? a2 : a3);
                fma2(acc2[p][0], a, b0);
                fma2(acc2[p][1], a, b1);
                fma2(acc2[p][2], a, b2);
                fma2(acc2[p][3], a, b3);
                fma2(acc2[p][4], a, b4);
                fma2(acc2[p][5], a, b5);
                fma2(acc2[p][6], a, b6);
                fma2(acc2[p][7], a, b7);
            }
        }
        __syncthreads();
    }

#pragma unroll
    for (int p = 0; p < 4; p++) {
        float2 e[8];
#pragma unroll
        for (int j = 0; j < 8; j++) e[j] = unpack2(acc2[p][j]);
        float* o0 = &out[(size_t)(m0 + ty * 8 + 2 * p) * DM + n0 + tx * 8];
        float4 v;
        v.x = e[0].x; v.y = e[1].x; v.z = e[2].x; v.w = e[3].x;
        *(float4*)&o0[0] = v;
        v.x = e[4].x; v.y = e[5].x; v.z = e[6].x; v.w = e[7].x;
        *(float4*)&o0[4] = v;
        float* o1 = o0 + DM;
        v.x = e[0].y; v.y = e[1].y; v.z = e[2].y; v.w = e[3].y;
        *(float4*)&o1[0] = v;
        v.x = e[4].y; v.y = e[5].y; v.z = e[6].y; v.w = e[7].y;
        *(float4*)&o1[4] = v;
    }
}

// ---------------------------------------------------------------------------
// launch
// ---------------------------------------------------------------------------
extern "C" void kernel_launch(void* const* d_in, const int* in_sizes, int n_in,
                              void* d_out, int out_size) {
    // metadata order (setup_inputs dict): x, Wk, Wq, Wv, Wo
    const float* x  = (const float*)d_in[0];
    const float* Wk = (const float*)d_in[1];
    const float* Wq = (const float*)d_in[2];
    const float* Wv = (const float*)d_in[3];
    const float* Wo = (const float*)d_in[4];
    float* out = (float*)d_out;

    static int attn_smem_set = 0;
    const size_t attn_smem = 4 * 64 * 68 * sizeof(float);   // 69,632 B
    if (!attn_smem_set) {
        cudaFuncSetAttribute(attn_kernel, cudaFuncAttributeMaxDynamicSharedMemorySize,
                             (int)attn_smem);
        attn_smem_set = 1;
    }

    qkv_kernel<<<dim3(MTOT / 128, 48), 256>>>(x, Wq, Wk, Wv);
    attn_kernel<<<dim3(SS / 64, BB * HH), 256, attn_smem>>>();
    outproj_kernel<<<dim3(MTOT / 128, DM / 128), 256>>>(Wo, out);
}

// round 13
// speedup vs baseline: 4.5849x; 4.5254x over previous
#include <cuda_runtime.h>
#include <cuda_bf16.h>

typedef unsigned int uint;

// Problem dims
#define BB 2
#define SS 2048
#define DM 1024
#define HH 16
#define DK 64
#define MTOT (BB*SS)   // 4096

// Single dynamic-smem symbol (bf16-typed) shared by all kernels.
extern __shared__ __nv_bfloat16 dsmem[];

// ---------------------------------------------------------------------------
// Scratch (device globals; no allocations allowed)
// ---------------------------------------------------------------------------
__device__ __nv_bfloat16 g_xh[(size_t)MTOT*DM];      // x split hi [m][k]
__device__ __nv_bfloat16 g_xl[(size_t)MTOT*DM];
__device__ __nv_bfloat16 g_wh[(size_t)48*DK*DM];     // W q/k/v as [z][n][k]
__device__ __nv_bfloat16 g_wl[(size_t)48*DK*DM];
__device__ __nv_bfloat16 g_woh[(size_t)DM*DM];       // Wo^T as [n][c]
__device__ __nv_bfloat16 g_wol[(size_t)DM*DM];
__device__ __nv_bfloat16 g_Qh[(size_t)32*SS*DK];     // [bh][t][dv] (pre-scaled 1/8)
__device__ __nv_bfloat16 g_Ql[(size_t)32*SS*DK];
__device__ __nv_bfloat16 g_Kh[(size_t)32*SS*DK];
__device__ __nv_bfloat16 g_Kl[(size_t)32*SS*DK];
__device__ __nv_bfloat16 g_Vh[(size_t)32*SS*DK];
__device__ __nv_bfloat16 g_Vl[(size_t)32*SS*DK];
__device__ __nv_bfloat16 g_Ch[(size_t)MTOT*DM];      // ctx [m][c=h*64+dv]
__device__ __nv_bfloat16 g_Cl[(size_t)MTOT*DM];

// ---------------------------------------------------------------------------
// helpers
// ---------------------------------------------------------------------------
// m16n8k16 row.col bf16 -> f32 accum (sm_80+ PTX; HMMA on sm_103)
__device__ __forceinline__ void mma16816(float4& c, const uint* a, const uint* b) {
    asm volatile("mma.sync.aligned.m16n8k16.row.col.f32.bf16.bf16.f32 "
        "{%0,%1,%2,%3}, {%4,%5,%6,%7}, {%8,%9}, {%0,%1,%2,%3};"
        : "+f"(c.x), "+f"(c.y), "+f"(c.z), "+f"(c.w)
        : "r"(a[0]), "r"(a[1]), "r"(a[2]), "r"(a[3]), "r"(b[0]), "r"(b[1]));
}

// fp32 -> bf16 hi/lo split
__device__ __forceinline__ void bsplit(float v, __nv_bfloat16& h, __nv_bfloat16& l) {
    h = __float2bfloat16(v);
    l = __float2bfloat16(v - __bfloat162float(h));
}
// split a pair (va, vb) -> packed hi-uint and lo-uint (va in lower 16 bits)
__device__ __forceinline__ void split2(float va, float vb, uint& uh, uint& ul) {
    __nv_bfloat162 H, L;
    bsplit(va, H.x, L.x);
    bsplit(vb, H.y, L.y);
    uh = *(uint*)&H;
    ul = *(uint*)&L;
}

#define SA 72   // smem tile row stride (bf16 elems): conflict-free frag loads

// ---------------------------------------------------------------------------
// Prep kernels: bf16 hi/lo splits of inputs
// ---------------------------------------------------------------------------
__global__ __launch_bounds__(256) void prep_x(const float* __restrict__ x) {
    int row = blockIdx.x, t = threadIdx.x;
    size_t base = (size_t)row * DM + t * 4;
    float4 v = *(const float4*)&x[base];
    union { __nv_bfloat16 b[4]; uint2 u; } H, L;
    bsplit(v.x, H.b[0], L.b[0]); bsplit(v.y, H.b[1], L.b[1]);
    bsplit(v.z, H.b[2], L.b[2]); bsplit(v.w, H.b[3], L.b[3]);
    *(uint2*)&g_xh[base] = H.u;
    *(uint2*)&g_xl[base] = L.u;
}

// W (q/k/v): [1024 k][64 n] fp32 -> [z][64 n][1024 k] bf16 hi/lo
__global__ __launch_bounds__(256) void prep_w(const float* __restrict__ Wq,
                                              const float* __restrict__ Wk,
                                              const float* __restrict__ Wv) {
    __shared__ float tile[32][33];
    int z = blockIdx.x, k0 = blockIdx.y * 32, n0 = blockIdx.z * 32;
    const float* W = (z < 16 ? Wq : (z < 32 ? Wk : Wv)) + (size_t)(z & 15) * DM * DK;
    int tx = threadIdx.x, ty = threadIdx.y;
#pragma unroll
    for (int i = 0; i < 4; i++)
        tile[ty + 8 * i][tx] = W[(size_t)(k0 + ty + 8 * i) * DK + n0 + tx];
    __syncthreads();
#pragma unroll
    for (int i = 0; i < 4; i++) {
        int nn = ty + 8 * i;
        __nv_bfloat16 h, l;
        bsplit(tile[tx][nn], h, l);
        size_t d = ((size_t)z * DK + n0 + nn) * DM + k0 + tx;
        g_wh[d] = h; g_wl[d] = l;
    }
}

// Wo: [1024 c][1024 n] fp32 -> [n][c] bf16 hi/lo
__global__ __launch_bounds__(256) void prep_wo(const float* __restrict__ Wo) {
    __shared__ float tile[32][33];
    int c0 = blockIdx.x * 32, n0 = blockIdx.y * 32;
    int tx = threadIdx.x, ty = threadIdx.y;
#pragma unroll
    for (int i = 0; i < 4; i++)
        tile[ty + 8 * i][tx] = Wo[(size_t)(c0 + ty + 8 * i) * DM + n0 + tx];
    __syncthreads();
#pragma unroll
    for (int i = 0; i < 4; i++) {
        int nn = ty + 8 * i;
        __nv_bfloat16 h, l;
        bsplit(tile[tx][nn], h, l);
        size_t d = (size_t)(n0 + nn) * DM + c0 + tx;
        g_woh[d] = h; g_wol[d] = l;
    }
}

// ---------------------------------------------------------------------------
// Kernel 1: QKV projection, mma.sync bf16x3 (hh + hl + lh).
// grid (32, 48): 128-row m-tile, z -> (mat, head). 256 thr = 8 warps (4m x 2n),
// warp tile 32x32 (2 m-frags x 4 n-frags). K chunks of 64.
// smem (bf16 elems): Ah@0[128][72], Al@9216, Bh@18432[64][72], Bl@23040 = 55296B
// ---------------------------------------------------------------------------
#define QKV_SMEM 55296
__global__ __launch_bounds__(256) void qkv_mma(void) {
    __nv_bfloat16* sAh = dsmem;
    __nv_bfloat16* sAl = dsmem + 9216;
    __nv_bfloat16* sBh = dsmem + 18432;
    __nv_bfloat16* sBl = dsmem + 23040;
    const int t = threadIdx.x, lane = t & 31, w = t >> 5;
    const int wm = w >> 1, wn = w & 1, g = lane >> 2, tig = lane & 3;
    const int m0 = blockIdx.x * 128, z = blockIdx.y;

    float4 c[2][4];
#pragma unroll
    for (int mi = 0; mi < 2; mi++)
#pragma unroll
        for (int nj = 0; nj < 4; nj++) c[mi][nj] = make_float4(0.f, 0.f, 0.f, 0.f);

    for (int ch = 0; ch < 16; ch++) {
        const int k0 = ch * 64;
#pragma unroll
        for (int i = 0; i < 8; i++) {
            int idx = t + i * 256, row = idx >> 4, c8 = (idx & 15) * 4;
            *(uint2*)&sAh[row * SA + c8] = *(const uint2*)&g_xh[(size_t)(m0 + row) * DM + k0 + c8];
            *(uint2*)&sAl[row * SA + c8] = *(const uint2*)&g_xl[(size_t)(m0 + row) * DM + k0 + c8];
        }
#pragma unroll
        for (int i = 0; i < 4; i++) {
            int idx = t + i * 256, row = idx >> 4, c8 = (idx & 15) * 4;
            *(uint2*)&sBh[row * SA + c8] = *(const uint2*)&g_wh[((size_t)z * DK + row) * DM + k0 + c8];
            *(uint2*)&sBl[row * SA + c8] = *(const uint2*)&g_wl[((size_t)z * DK + row) * DM + k0 + c8];
        }
        __syncthreads();

#pragma unroll
        for (int ks = 0; ks < 4; ks++) {
            const int kb = ks * 16;
            uint ah[2][4], al[2][4], bh[4][2], bl[4][2];
#pragma unroll
            for (int mi = 0; mi < 2; mi++) {
                int rb = wm * 32 + mi * 16 + g;
                const __nv_bfloat16* ph = &sAh[rb * SA + kb + 2 * tig];
                ah[mi][0] = *(const uint*)ph;            ah[mi][1] = *(const uint*)(ph + 8 * SA);
                ah[mi][2] = *(const uint*)(ph + 8);      ah[mi][3] = *(const uint*)(ph + 8 * SA + 8);
                const __nv_bfloat16* pl = &sAl[rb * SA + kb + 2 * tig];
                al[mi][0] = *(const uint*)pl;            al[mi][1] = *(const uint*)(pl + 8 * SA);
                al[mi][2] = *(const uint*)(pl + 8);      al[mi][3] = *(const uint*)(pl + 8 * SA + 8);
            }
#pragma unroll
            for (int nj = 0; nj < 4; nj++) {
                int rn = wn * 32 + nj * 8 + g;
                const __nv_bfloat16* ph = &sBh[rn * SA + kb + 2 * tig];
                bh[nj][0] = *(const uint*)ph; bh[nj][1] = *(const uint*)(ph + 8);
                const __nv_bfloat16* pl = &sBl[rn * SA + kb + 2 * tig];
                bl[nj][0] = *(const uint*)pl; bl[nj][1] = *(const uint*)(pl + 8);
            }
#pragma unroll
            for (int mi = 0; mi < 2; mi++)
#pragma unroll
                for (int nj = 0; nj < 4; nj++) {
                    mma16816(c[mi][nj], ah[mi], bh[nj]);
                    mma16816(c[mi][nj], ah[mi], bl[nj]);
                    mma16816(c[mi][nj], al[mi], bh[nj]);
                }
        }
        __syncthreads();
    }

    // epilogue -> bf16 hi/lo Q/K/V, [bh][t][dv]; Q pre-scaled by 1/8 (exact)
    __nv_bfloat16* Oh = (z < 16 ? g_Qh : (z < 32 ? g_Kh : g_Vh));
    __nv_bfloat16* Ol = (z < 16 ? g_Ql : (z < 32 ? g_Kl : g_Vl));
    const int h = z & 15;
    const float scale = (z < 16) ? 0.125f : 1.0f;
#pragma unroll
    for (int mi = 0; mi < 2; mi++)
#pragma unroll
        for (int nj = 0; nj < 4; nj++) {
            int r0 = m0 + wm * 32 + mi * 16 + g;
            int col = wn * 32 + nj * 8 + 2 * tig;
            int b = r0 >> 11, s = r0 & 2047;
            size_t d0 = (((size_t)(b * HH + h)) * SS + s) * DK + col;
            uint uh, ul;
            split2(c[mi][nj].x * scale, c[mi][nj].y * scale, uh, ul);
            *(uint*)&Oh[d0] = uh; *(uint*)&Ol[d0] = ul;
            size_t d1 = d0 + 8 * DK;   // row r0+8, same b (rows within 128-tile)
            split2(c[mi][nj].z * scale, c[mi][nj].w * scale, uh, ul);
            *(uint*)&Oh[d1] = uh; *(uint*)&Ol[d1] = ul;
        }
}

// ---------------------------------------------------------------------------
// Kernel 2: flash attention, mma.sync bf16x3 for QK and PV.
// grid (16, 32): 128 q-rows x bh. 128 thr = 4 warps, warp = 32 q-rows x all 64.
// smem: Qh@0[128][72] Ql@9216 Kh@18432[64][72] Kl@23040 Vth@27648 Vtl@32256
//   = 36864 elems = 73728 B. Vt is V transposed: [dv][t_local].
// ---------------------------------------------------------------------------
#define ATT_SMEM 73728
__global__ __launch_bounds__(128) void attn_mma(void) {
    __nv_bfloat16* sQh  = dsmem;
    __nv_bfloat16* sQl  = dsmem + 9216;
    __nv_bfloat16* sKh  = dsmem + 18432;
    __nv_bfloat16* sKl  = dsmem + 23040;
    __nv_bfloat16* sVth = dsmem + 27648;
    __nv_bfloat16* sVtl = dsmem + 32256;

    const int t = threadIdx.x, lane = t & 31, wm = t >> 5;
    const int g = lane >> 2, tig = lane & 3;
    const int q0 = blockIdx.x * 128, bh = blockIdx.y;
    const size_t hb = (size_t)bh * SS * DK;

    // load Q tile (already 1/8-scaled)
#pragma unroll
    for (int i = 0; i < 16; i++) {
        int idx = t + i * 128, row = idx >> 4, c8 = (idx & 15) * 4;
        *(uint2*)&sQh[row * SA + c8] = *(const uint2*)&g_Qh[hb + (size_t)(q0 + row) * DK + c8];
        *(uint2*)&sQl[row * SA + c8] = *(const uint2*)&g_Ql[hb + (size_t)(q0 + row) * DK + c8];
    }

    float4 o[2][8];
#pragma unroll
    for (int mi = 0; mi < 2; mi++)
#pragma unroll
        for (int nj = 0; nj < 8; nj++) o[mi][nj] = make_float4(0.f, 0.f, 0.f, 0.f);
    float mrun[4] = {-3.0e38f, -3.0e38f, -3.0e38f, -3.0e38f};
    float lrun[4] = {0.f, 0.f, 0.f, 0.f};

    for (int t0 = 0; t0 < SS; t0 += 64) {
        __syncthreads();   // prev PV done with K/V tiles (covers Q load too)
#pragma unroll
        for (int i = 0; i < 8; i++) {
            int idx = t + i * 128, row = idx >> 4, c8 = (idx & 15) * 4;
            *(uint2*)&sKh[row * SA + c8] = *(const uint2*)&g_Kh[hb + (size_t)(t0 + row) * DK + c8];
            *(uint2*)&sKl[row * SA + c8] = *(const uint2*)&g_Kl[hb + (size_t)(t0 + row) * DK + c8];
        }
        // V transpose: [t][dv] -> Vt[dv][t]
#pragma unroll
        for (int i = 0; i < 16; i++) {
            int idx = t + i * 128, tr = idx >> 5, d2 = (idx & 31) * 2;
            uint uh = *(const uint*)&g_Vh[hb + (size_t)(t0 + tr) * DK + d2];
            uint ul = *(const uint*)&g_Vl[hb + (size_t)(t0 + tr) * DK + d2];
            sVth[d2 * SA + tr]       = ((__nv_bfloat16*)&uh)[0];
            sVth[(d2 + 1) * SA + tr] = ((__nv_bfloat16*)&uh)[1];
            sVtl[d2 * SA + tr]       = ((__nv_bfloat16*)&ul)[0];
            sVtl[(d2 + 1) * SA + tr] = ((__nv_bfloat16*)&ul)[1];
        }
        __syncthreads();

        // ---- S = Q K^T (bf16x3) ----
        float4 s[2][8];
#pragma unroll
        for (int mi = 0; mi < 2; mi++)
#pragma unroll
            for (int nj = 0; nj < 8; nj++) s[mi][nj] = make_float4(0.f, 0.f, 0.f, 0.f);
#pragma unroll
        for (int ks = 0; ks < 4; ks++) {
            const int kb = ks * 16;
            uint ah[2][4], al[2][4], bkh[8][2], bkl[8][2];
#pragma unroll
            for (int mi = 0; mi < 2; mi++) {
                int rb = wm * 32 + mi * 16 + g;
                const __nv_bfloat16* ph = &sQh[rb * SA + kb + 2 * tig];
                ah[mi][0] = *(const uint*)ph;       ah[mi][1] = *(const uint*)(ph + 8 * SA);
                ah[mi][2] = *(const uint*)(ph + 8); ah[mi][3] = *(const uint*)(ph + 8 * SA + 8);
                const __nv_bfloat16* pl = &sQl[rb * SA + kb + 2 * tig];
                al[mi][0] = *(const uint*)pl;       al[mi][1] = *(const uint*)(pl + 8 * SA);
                al[mi][2] = *(const uint*)(pl + 8); al[mi][3] = *(const uint*)(pl + 8 * SA + 8);
            }
#pragma unroll
            for (int nj = 0; nj < 8; nj++) {
                int rn = nj * 8 + g;
                const __nv_bfloat16* ph = &sKh[rn * SA + kb + 2 * tig];
                bkh[nj][0] = *(const uint*)ph; bkh[nj][1] = *(const uint*)(ph + 8);
                const __nv_bfloat16* pl = &sKl[rn * SA + kb + 2 * tig];
                bkl[nj][0] = *(const uint*)pl; bkl[nj][1] = *(const uint*)(pl + 8);
            }
#pragma unroll
            for (int mi = 0; mi < 2; mi++)
#pragma unroll
                for (int nj = 0; nj < 8; nj++) {
                    mma16816(s[mi][nj], ah[mi], bkh[nj]);
                    mma16816(s[mi][nj], ah[mi], bkl[nj]);
                    mma16816(s[mi][nj], al[mi], bkh[nj]);
                }
        }

        // ---- online softmax in fragments (4 lanes per row: shfl 1,2) ----
        float cor[4];
#pragma unroll
        for (int mi = 0; mi < 2; mi++)
#pragma unroll
            for (int half = 0; half < 2; half++) {
                int idx = mi * 2 + half;
                float mloc = -3.0e38f;
#pragma unroll
                for (int nj = 0; nj < 8; nj++) {
                    float va = half ? s[mi][nj].z : s[mi][nj].x;
                    float vb = half ? s[mi][nj].w : s[mi][nj].y;
                    mloc = fmaxf(mloc, fmaxf(va, vb));
                }
                mloc = fmaxf(mloc, __shfl_xor_sync(0xffffffffu, mloc, 1));
                mloc = fmaxf(mloc, __shfl_xor_sync(0xffffffffu, mloc, 2));
                float mnew = fmaxf(mrun[idx], mloc);
                float corr = __expf(mrun[idx] - mnew);
                mrun[idx] = mnew;
                float lloc = 0.f;
#pragma unroll
                for (int nj = 0; nj < 8; nj++) {
                    if (half == 0) {
                        s[mi][nj].x = __expf(s[mi][nj].x - mnew);
                        s[mi][nj].y = __expf(s[mi][nj].y - mnew);
                        lloc += s[mi][nj].x + s[mi][nj].y;
                    } else {
                        s[mi][nj].z = __expf(s[mi][nj].z - mnew);
                        s[mi][nj].w = __expf(s[mi][nj].w - mnew);
                        lloc += s[mi][nj].z + s[mi][nj].w;
                    }
                }
                lloc += __shfl_xor_sync(0xffffffffu, lloc, 1);
                lloc += __shfl_xor_sync(0xffffffffu, lloc, 2);
                lrun[idx] = lrun[idx] * corr + lloc;
                cor[idx] = corr;
            }
#pragma unroll
        for (int mi = 0; mi < 2; mi++)
#pragma unroll
            for (int nj = 0; nj < 8; nj++) {
                o[mi][nj].x *= cor[mi * 2];     o[mi][nj].y *= cor[mi * 2];
                o[mi][nj].z *= cor[mi * 2 + 1]; o[mi][nj].w *= cor[mi * 2 + 1];
            }

        // ---- O += P V (P hi/lo built in-register; bf16x3) ----
#pragma unroll
        for (int kk = 0; kk < 4; kk++) {
            const int kb = kk * 16;
            uint bvh[8][2], bvl[8][2];
#pragma unroll
            for (int nj = 0; nj < 8; nj++) {
                int rn = nj * 8 + g;
                const __nv_bfloat16* ph = &sVth[rn * SA + kb + 2 * tig];
                bvh[nj][0] = *(const uint*)ph; bvh[nj][1] = *(const uint*)(ph + 8);
                const __nv_bfloat16* pl = &sVtl[rn * SA + kb + 2 * tig];
                bvl[nj][0] = *(const uint*)pl; bvl[nj][1] = *(const uint*)(pl + 8);
            }
#pragma unroll
            for (int mi = 0; mi < 2; mi++) {
                uint pah[4], pal[4];
                split2(s[mi][2 * kk].x,     s[mi][2 * kk].y,     pah[0], pal[0]);
                split2(s[mi][2 * kk].z,     s[mi][2 * kk].w,     pah[1], pal[1]);
                split2(s[mi][2 * kk + 1].x, s[mi][2 * kk + 1].y, pah[2], pal[2]);
                split2(s[mi][2 * kk + 1].z, s[mi][2 * kk + 1].w, pah[3], pal[3]);
#pragma unroll
                for (int nj = 0; nj < 8; nj++) {
                    mma16816(o[mi][nj], pah, bvh[nj]);
                    mma16816(o[mi][nj], pah, bvl[nj]);
                    mma16816(o[mi][nj], pal, bvh[nj]);
                }
            }
        }
    }

    // epilogue: normalize, split, store ctx [m][c = h*64 + dv]
    float inv[4];
#pragma unroll
    for (int i = 0; i < 4; i++) inv[i] = 1.f / lrun[i];
    const int b = bh >> 4, h = bh & 15;
#pragma unroll
    for (int mi = 0; mi < 2; mi++)
#pragma unroll
        for (int nj = 0; nj < 8; nj++) {
            int r0 = q0 + wm * 32 + mi * 16 + g;
            int col = nj * 8 + 2 * tig;
            size_t d0 = ((size_t)b * SS + r0) * DM + h * DK + col;
            uint uh, ul;
            split2(o[mi][nj].x * inv[mi * 2], o[mi][nj].y * inv[mi * 2], uh, ul);
            *(uint*)&g_Ch[d0] = uh; *(uint*)&g_Cl[d0] = ul;
            size_t d1 = d0 + 8 * DM;
            split2(o[mi][nj].z * inv[mi * 2 + 1], o[mi][nj].w * inv[mi * 2 + 1], uh, ul);
            *(uint*)&g_Ch[d1] = uh; *(uint*)&g_Cl[d1] = ul;
        }
}

// ---------------------------------------------------------------------------
// Kernel 3: output projection, mma.sync bf16x3. out = ctx[4096x1024] x Wo.
// grid (32, 8): m-tile 128 x n-tile 128. 256 thr = 8 warps (4m x 2n),
// warp 32x64 (2 m-frags x 8 n-frags). K chunks of 64.
// smem: Ah@0[128][72] Al@9216 Bh@18432[128][72] Bl@27648 = 73728 B
// ---------------------------------------------------------------------------
#define OP_SMEM 73728
__global__ __launch_bounds__(256) void outproj_mma(float* __restrict__ out) {
    __nv_bfloat16* sAh = dsmem;
    __nv_bfloat16* sAl = dsmem + 9216;
    __nv_bfloat16* sBh = dsmem + 18432;
    __nv_bfloat16* sBl = dsmem + 27648;
    const int t = threadIdx.x, lane = t & 31, w = t >> 5;
    const int wm = w >> 1, wn = w & 1, g = lane >> 2, tig = lane & 3;
    const int m0 = blockIdx.x * 128, n0 = blockIdx.y * 128;

    float4 c[2][8];
#pragma unroll
    for (int mi = 0; mi < 2; mi++)
#pragma unroll
        for (int nj = 0; nj < 8; nj++) c[mi][nj] = make_float4(0.f, 0.f, 0.f, 0.f);

    for (int ch = 0; ch < 16; ch++) {
        const int k0 = ch * 64;
#pragma unroll
        for (int i = 0; i < 8; i++) {
            int idx = t + i * 256, row = idx >> 4, c8 = (idx & 15) * 4;
            *(uint2*)&sAh[row * SA + c8] = *(const uint2*)&g_Ch[(size_t)(m0 + row) * DM + k0 + c8];
            *(uint2*)&sAl[row * SA + c8] = *(const uint2*)&g_Cl[(size_t)(m0 + row) * DM + k0 + c8];
            *(uint2*)&sBh[row * SA + c8] = *(const uint2*)&g_woh[(size_t)(n0 + row) * DM + k0 + c8];
            *(uint2*)&sBl[row * SA + c8] = *(const uint2*)&g_wol[(size_t)(n0 + row) * DM + k0 + c8];
        }
        __syncthreads();

#pragma unroll
        for (int ks = 0; ks < 4; ks++) {
            const int kb = ks * 16;
            uint ah[2][4], al[2][4], bh[8][2], bl[8][2];
#pragma unroll
            for (int mi = 0; mi < 2; mi++) {
                int rb = wm * 32 + mi * 16 + g;
                const __nv_bfloat16* ph = &sAh[rb * SA + kb + 2 * tig];
                ah[mi][0] = *(const uint*)ph;       ah[mi][1] = *(const uint*)(ph + 8 * SA);
                ah[mi][2] = *(const uint*)(ph + 8); ah[mi][3] = *(const uint*)(ph + 8 * SA + 8);
                const __nv_bfloat16* pl = &sAl[rb * SA + kb + 2 * tig];
                al[mi][0] = *(const uint*)pl;       al[mi][1] = *(const uint*)(pl + 8 * SA);
                al[mi][2] = *(const uint*)(pl + 8); al[mi][3] = *(const uint*)(pl + 8 * SA + 8);
            }
#pragma unroll
            for (int nj = 0; nj < 8; nj++) {
                int rn = wn * 64 + nj * 8 + g;
                const __nv_bfloat16* ph = &sBh[rn * SA + kb + 2 * tig];
                bh[nj][0] = *(const uint*)ph; bh[nj][1] = *(const uint*)(ph + 8);
                const __nv_bfloat16* pl = &sBl[rn * SA + kb + 2 * tig];
                bl[nj][0] = *(const uint*)pl; bl[nj][1] = *(const uint*)(pl + 8);
            }
#pragma unroll
            for (int mi = 0; mi < 2; mi++)
#pragma unroll
                for (int nj = 0; nj < 8; nj++) {
                    mma16816(c[mi][nj], ah[mi], bh[nj]);
                    mma16816(c[mi][nj], ah[mi], bl[nj]);
                    mma16816(c[mi][nj], al[mi], bh[nj]);
                }
        }
        __syncthreads();
    }

    // epilogue: fp32 out
#pragma unroll
    for (int mi = 0; mi < 2; mi++)
#pragma unroll
        for (int nj = 0; nj < 8; nj++) {
            int r0 = m0 + wm * 32 + mi * 16 + g;
            int col = n0 + wn * 64 + nj * 8 + 2 * tig;
            float2 v0 = make_float2(c[mi][nj].x, c[mi][nj].y);
            *(float2*)&out[(size_t)r0 * DM + col] = v0;
            float2 v1 = make_float2(c[mi][nj].z, c[mi][nj].w);
            *(float2*)&out[(size_t)(r0 + 8) * DM + col] = v1;
        }
}

// ---------------------------------------------------------------------------
// launch
// ---------------------------------------------------------------------------
extern "C" void kernel_launch(void* const* d_in, const int* in_sizes, int n_in,
                              void* d_out, int out_size) {
    // metadata order (setup_inputs dict): x, Wk, Wq, Wv, Wo
    const float* x  = (const float*)d_in[0];
    const float* Wk = (const float*)d_in[1];
    const float* Wq = (const float*)d_in[2];
    const float* Wv = (const float*)d_in[3];
    const float* Wo = (const float*)d_in[4];
    float* out = (float*)d_out;

    static int attrs_set = 0;
    if (!attrs_set) {
        cudaFuncSetAttribute(qkv_mma, cudaFuncAttributeMaxDynamicSharedMemorySize, QKV_SMEM);
        cudaFuncSetAttribute(attn_mma, cudaFuncAttributeMaxDynamicSharedMemorySize, ATT_SMEM);
        cudaFuncSetAttribute(outproj_mma, cudaFuncAttributeMaxDynamicSharedMemorySize, OP_SMEM);
        attrs_set = 1;
    }

    prep_x<<<MTOT, 256>>>(x);
    prep_w<<<dim3(48, 32, 2), dim3(32, 8)>>>(Wq, Wk, Wv);
    prep_wo<<<dim3(32, 32), dim3(32, 8)>>>(Wo);
    qkv_mma<<<dim3(MTOT / 128, 48), 256, QKV_SMEM>>>();
    attn_mma<<<dim3(SS / 128, BB * HH), 128, ATT_SMEM>>>();
    outproj_mma<<<dim3(MTOT / 128, DM / 128), 256, OP_SMEM>>>(out);
}